// round 4
// baseline (speedup 1.0000x reference)
#include <cuda_runtime.h>
#include <cstdint>

// LIIF render via warp-level tf32 HMMA (mma.sync m16n8k8) on sm_103.
// R4: layer-0 folded into a per-image precomputed projection P' (4096 distinct
// feature cells), gathered coalesced; 512 threads, 32x64 warp tiles (16 warps);
// layers 1-3 as tf32 HMMA with cp.async double-buffered weight K-tiles.

namespace {

constexpr int NTHR      = 512;
constexpr int QT        = 32;
constexpr int XS_STRIDE = 260;               // %32==4 -> A reads conflict-free
constexpr int WS_STRIDE = 264;               // %32==8 -> B reads conflict-free
constexpr int WS_BUF    = 32 * WS_STRIDE;
constexpr int NSTAGES   = 24;                // layers 1..3, K-tiles of 32

__device__ float g_wr[196608];               // tf32-rounded w1..w3, [k][256]
__device__ float g_proj[4 * 4096 * 256];     // P' = feat@w0f + b0 + cell-terms (fp32)

__device__ __forceinline__ uint32_t smem_u32(const void* p) {
    uint32_t a;
    asm("{ .reg .u64 t; cvta.to.shared.u64 t, %1; cvt.u32.u64 %0, t; }"
        : "=r"(a) : "l"(p));
    return a;
}
__device__ __forceinline__ float tf32r(float x) {
    float y; asm("cvt.rna.tf32.f32 %0, %1;" : "=f"(y) : "f"(x)); return y;
}
__device__ __forceinline__ void cp16(uint32_t dst, const void* src) {
    asm volatile("cp.async.cg.shared.global [%0], [%1], 16;"
                 :: "r"(dst), "l"(src) : "memory");
}
__device__ __forceinline__ void cp_commit() {
    asm volatile("cp.async.commit_group;" ::: "memory");
}
template <int N>
__device__ __forceinline__ void cp_wait() {
    asm volatile("cp.async.wait_group %0;" :: "n"(N) : "memory");
}
__device__ __forceinline__ void mma_tf32(float c[4], uint32_t a0, uint32_t a1,
                                         uint32_t a2, uint32_t a3,
                                         uint32_t b0, uint32_t b1) {
    asm volatile(
        "mma.sync.aligned.m16n8k8.row.col.f32.tf32.tf32.f32 "
        "{%0,%1,%2,%3}, {%4,%5,%6,%7}, {%8,%9}, {%0,%1,%2,%3};"
        : "+f"(c[0]), "+f"(c[1]), "+f"(c[2]), "+f"(c[3])
        : "r"(a0), "r"(a1), "r"(a2), "r"(a3), "r"(b0), "r"(b1));
}

// ---------- prep 1: tf32-round w1..w3 into [k][256] scratch ----------
__global__ void prep_w_kernel(const float* __restrict__ w1, const float* __restrict__ w2,
                              const float* __restrict__ w3) {
    const int idx = blockIdx.x * blockDim.x + threadIdx.x;
    if (idx >= 196608) return;
    const int l = idx >> 16;
    const float* w = (l == 0) ? w1 : (l == 1) ? w2 : w3;
    g_wr[idx] = tf32r(w[idx & 65535]);
}

// ---------- prep 2: P'[n][idx][c] = sum_ch feat[n][ch][idx]*w0[ch][c]
//                                   + b0[c] + 0.5*(w0[66][c]+w0[67][c]) ----------
__global__ void prep_proj_kernel(const float* __restrict__ feat,
                                 const float* __restrict__ w0,
                                 const float* __restrict__ b0) {
    __shared__ float sf[64];
    const int blk = blockIdx.x;              // 0..16383 = n*4096 + idx
    const int n   = blk >> 12;
    const int idx = blk & 4095;
    const int c   = threadIdx.x;             // 0..255
    if (c < 64) sf[c] = feat[((size_t)n * 64 + c) * 4096 + idx];
    __syncthreads();
    float acc = b0[c] + 0.5f * (w0[66 * 256 + c] + w0[67 * 256 + c]);
#pragma unroll 8
    for (int ch = 0; ch < 64; ch++)
        acc = fmaf(sf[ch], w0[ch * 256 + c], acc);
    g_proj[(size_t)blk * 256 + c] = acc;
}

// ---------- main kernel ----------
__global__ __launch_bounds__(NTHR, 1)
void liif_hmma_kernel(const float* __restrict__ w0, const float* __restrict__ w4,
                      const float* __restrict__ b1, const float* __restrict__ b2,
                      const float* __restrict__ b3, const float* __restrict__ b4,
                      float* __restrict__ out)
{
    extern __shared__ float smem[];
    float* Xs = smem;                             // 128 x 260
    float* Ws = smem + 128 * XS_STRIDE;           // 2 x WS_BUF
    const uint32_t ws_u = smem_u32(Ws);

    __shared__ float s_bias[3][256];
    __shared__ float s_w0r[2][256];               // w0 rows 64, 65 (rel terms)
    __shared__ float s_w4[772];
    __shared__ float s_b4[3];
    __shared__ int   s_idx[4][QT];
    __shared__ float s_rel[4][2][QT];
    __shared__ float s_wt[4][QT];
    __shared__ float s_red[128][4][3];

    const int tid  = threadIdx.x;
    const int wid  = tid >> 5;
    const int lane = tid & 31;
    const int n    = blockIdx.y;
    const int q0   = blockIdx.x * QT;

    // prime stage-0 weight copy
    {
        const float* src = g_wr;
#pragma unroll
        for (int j = 0; j < 4; j++) {
            const int i   = tid + NTHR * j;
            const int row = i >> 6, f4 = i & 63;
            cp16(ws_u + (uint32_t)(row * WS_STRIDE + f4 * 4) * 4u, src + row * 256 + f4 * 4);
        }
        cp_commit();
    }

    for (int i = tid; i < 256; i += NTHR) {
        s_bias[0][i] = b1[i]; s_bias[1][i] = b2[i]; s_bias[2][i] = b3[i];
        s_w0r[0][i] = w0[64 * 256 + i]; s_w0r[1][i] = w0[65 * 256 + i];
    }
    if (tid < 256) { if (tid < 3) s_b4[tid] = b4[tid]; }
    for (int i = tid; i < 768; i += NTHR) s_w4[i] = w4[i];

    // per-query geometry (validated R1/R3)
    if (tid < QT) {
        const int q = q0 + tid;
        const int yq = q >> 8, xq = q & 255;
        const float c0 = (2.f * (float)yq + 1.f) * (1.f / 256.f) - 1.f;
        const float c1 = (2.f * (float)xq + 1.f) * (1.f / 256.f) - 1.f;
        const float lo = (float)(-1.0 + 1e-6), hi = (float)(1.0 - 1e-6);
        float areas[4];
#pragma unroll
        for (int t = 0; t < 4; t++) {
            const double vx = (t < 2) ? -1.0 : 1.0;
            const double vy = (t & 1) ? 1.0 : -1.0;
            const float shx = (float)(vx * (1.0 / 64.0) + 1e-6);
            const float shy = (float)(vy * (1.0 / 64.0) + 1e-6);
            const float cc0 = fminf(fmaxf(c0 + shx, lo), hi);
            const float cc1 = fminf(fmaxf(c1 + shy, lo), hi);
            int iy = (int)rintf(((cc0 + 1.f) * 64.f - 1.f) * 0.5f);
            int ix = (int)rintf(((cc1 + 1.f) * 64.f - 1.f) * 0.5f);
            iy = min(max(iy, 0), 63); ix = min(max(ix, 0), 63);
            const float qc0 = (2.f * (float)iy + 1.f) * (1.f / 64.f) - 1.f;
            const float qc1 = (2.f * (float)ix + 1.f) * (1.f / 64.f) - 1.f;
            const float r0 = (c0 - qc0) * 64.f;
            const float r1 = (c1 - qc1) * 64.f;
            s_idx[t][tid] = iy * 64 + ix;
            s_rel[t][0][tid] = r0; s_rel[t][1][tid] = r1;
            areas[t] = fabsf(r0 * r1) + 1e-9f;
        }
        const float tot = areas[0] + areas[1] + areas[2] + areas[3];
#pragma unroll
        for (int t = 0; t < 4; t++) s_wt[t][tid] = areas[3 - t] / tot;
    }
    __syncthreads();

    // h0 build: row = corner*32 + query; thread = (row, quarter of 64 cols).
    // h0 = relu(P'[idx] + rel0*w0[64] + rel1*w0[65]), fp32 then tf32-rounded.
    {
        const int row = tid >> 2, qu = tid & 3;
        const int t = row >> 5, i = row & 31;
        const int idx = s_idx[t][i];
        const float r0 = s_rel[t][0][i], r1 = s_rel[t][1][i];
        const float4* pp = (const float4*)(g_proj + (((size_t)n << 12) + idx) * 256) + qu * 16;
        float* xr = Xs + row * XS_STRIDE + qu * 64;
#pragma unroll
        for (int j = 0; j < 16; j++) {
            const float4 p = pp[j];
            const int c = qu * 64 + j * 4;
            float v0 = fmaf(r0, s_w0r[0][c],     fmaf(r1, s_w0r[1][c],     p.x));
            float v1 = fmaf(r0, s_w0r[0][c + 1], fmaf(r1, s_w0r[1][c + 1], p.y));
            float v2 = fmaf(r0, s_w0r[0][c + 2], fmaf(r1, s_w0r[1][c + 2], p.z));
            float v3 = fmaf(r0, s_w0r[0][c + 3], fmaf(r1, s_w0r[1][c + 3], p.w));
            xr[j * 4]     = tf32r(fmaxf(v0, 0.f));
            xr[j * 4 + 1] = tf32r(fmaxf(v1, 0.f));
            xr[j * 4 + 2] = tf32r(fmaxf(v2, 0.f));
            xr[j * 4 + 3] = tf32r(fmaxf(v3, 0.f));
        }
    }
    __syncthreads();

    // warp tiling: 16 warps = 4 row-blocks(32) x 4 col-blocks(64)
    const int wm = wid & 3, wn = wid >> 2;
    const int g_ = lane >> 2, tig = lane & 3;
    const uint32_t* Arow = (const uint32_t*)(Xs + (wm * 32 + g_) * XS_STRIDE + tig);

    float acc[2][8][4];
#pragma unroll
    for (int mt = 0; mt < 2; mt++)
#pragma unroll
        for (int nt = 0; nt < 8; nt++)
#pragma unroll
            for (int r = 0; r < 4; r++) acc[mt][nt][r] = 0.f;

    int buf = 0;
#pragma unroll 1
    for (int st = 0; st < NSTAGES; st++) {
        const int tile = st & 7;

        if (st + 1 < NSTAGES) {
            const float* src = g_wr + (st + 1) * 8192;
            const uint32_t dst = ws_u + (uint32_t)(buf ^ 1) * (WS_BUF * 4);
#pragma unroll
            for (int j = 0; j < 4; j++) {
                const int i   = tid + NTHR * j;
                const int row = i >> 6, f4 = i & 63;
                cp16(dst + (uint32_t)(row * WS_STRIDE + f4 * 4) * 4u, src + row * 256 + f4 * 4);
            }
            cp_commit();
            cp_wait<1>();
        } else {
            cp_wait<0>();
        }
        __syncthreads();

        const uint32_t* Wb = (const uint32_t*)(Ws + buf * WS_BUF)
                             + tig * WS_STRIDE + wn * 64 + g_;
        const uint32_t* Ab = Arow + tile * 32;

#pragma unroll
        for (int k8 = 0; k8 < 4; k8++) {
            const uint32_t* Ak = Ab + k8 * 8;
            uint32_t a[2][4];
#pragma unroll
            for (int mt = 0; mt < 2; mt++) {
                a[mt][0] = Ak[(mt * 16)     * XS_STRIDE];
                a[mt][1] = Ak[(mt * 16 + 8) * XS_STRIDE];
                a[mt][2] = Ak[(mt * 16)     * XS_STRIDE + 4];
                a[mt][3] = Ak[(mt * 16 + 8) * XS_STRIDE + 4];
            }
            const uint32_t* Bk = Wb + k8 * 8 * WS_STRIDE;
#pragma unroll
            for (int nt = 0; nt < 8; nt++) {
                const uint32_t bb0 = Bk[nt * 8];
                const uint32_t bb1 = Bk[4 * WS_STRIDE + nt * 8];
#pragma unroll
                for (int mt = 0; mt < 2; mt++)
                    mma_tf32(acc[mt][nt], a[mt][0], a[mt][1], a[mt][2], a[mt][3], bb0, bb1);
            }
        }
        __syncthreads();   // all warps done reading Xs / this W buffer

        if (tile == 7) {   // layer epilogue: bias + relu (+tf32 round except last)
            const int le = st >> 3;
            const bool last = (st == NSTAGES - 1);
#pragma unroll
            for (int mt = 0; mt < 2; mt++) {
                const int r0 = wm * 32 + mt * 16 + g_;
#pragma unroll
                for (int nt = 0; nt < 8; nt++) {
                    const int c = wn * 64 + nt * 8 + 2 * tig;
                    const float bv0 = s_bias[le][c], bv1 = s_bias[le][c + 1];
                    float v00 = fmaxf(acc[mt][nt][0] + bv0, 0.f);
                    float v01 = fmaxf(acc[mt][nt][1] + bv1, 0.f);
                    float v10 = fmaxf(acc[mt][nt][2] + bv0, 0.f);
                    float v11 = fmaxf(acc[mt][nt][3] + bv1, 0.f);
                    if (!last) { v00 = tf32r(v00); v01 = tf32r(v01);
                                 v10 = tf32r(v10); v11 = tf32r(v11); }
                    Xs[r0 * XS_STRIDE + c]           = v00;
                    Xs[r0 * XS_STRIDE + c + 1]       = v01;
                    Xs[(r0 + 8) * XS_STRIDE + c]     = v10;
                    Xs[(r0 + 8) * XS_STRIDE + c + 1] = v11;
                    acc[mt][nt][0] = 0.f; acc[mt][nt][1] = 0.f;
                    acc[mt][nt][2] = 0.f; acc[mt][nt][3] = 0.f;
                }
            }
            __syncthreads();
        }
        buf ^= 1;
    }

    // final 256->3 layer, fp32: thread = (row, k-quarter), 3 accumulators
    {
        const int row = tid >> 2, qu = tid & 3;
        const float* xr = Xs + row * XS_STRIDE + qu * 64;
        float a0 = 0.f, a1 = 0.f, a2 = 0.f;
#pragma unroll 16
        for (int k = 0; k < 64; k++) {
            const float y = xr[k];
            const float* wr = &s_w4[(qu * 64 + k) * 3];
            a0 = fmaf(y, wr[0], a0);
            a1 = fmaf(y, wr[1], a1);
            a2 = fmaf(y, wr[2], a2);
        }
        s_red[row][qu][0] = a0; s_red[row][qu][1] = a1; s_red[row][qu][2] = a2;
    }
    __syncthreads();

    // reduce quarters, area-weighted combine, NCHW write
    if (tid < 96) {
        const int i = tid / 3;
        const int o = tid - 3 * (tid / 3);
        float v = 0.f;
#pragma unroll
        for (int t = 0; t < 4; t++) {
            const int row = t * 32 + i;
            const float p = s_b4[o] + s_red[row][0][o] + s_red[row][1][o]
                          + s_red[row][2][o] + s_red[row][3][o];
            v += s_wt[t][i] * p;
        }
        out[((size_t)n * 3 + o) * 65536 + q0 + i] = v;
    }
}

} // anonymous namespace

extern "C" void kernel_launch(void* const* d_in, const int* in_sizes, int n_in,
                              void* d_out, int out_size)
{
    (void)in_sizes; (void)n_in; (void)out_size;
    const float* feat = (const float*)d_in[0];
    const float* w0 = (const float*)d_in[1];
    const float* b0 = (const float*)d_in[2];
    const float* w1 = (const float*)d_in[3];
    const float* b1 = (const float*)d_in[4];
    const float* w2 = (const float*)d_in[5];
    const float* b2 = (const float*)d_in[6];
    const float* w3 = (const float*)d_in[7];
    const float* b3 = (const float*)d_in[8];
    const float* w4 = (const float*)d_in[9];
    const float* b4 = (const float*)d_in[10];

    prep_w_kernel<<<(196608 + 255) / 256, 256>>>(w1, w2, w3);
    prep_proj_kernel<<<16384, 256>>>(feat, w0, b0);

    const size_t shmem = (size_t)(128 * XS_STRIDE + 2 * WS_BUF) * sizeof(float); // 200704 B
    cudaFuncSetAttribute(liif_hmma_kernel,
                         cudaFuncAttributeMaxDynamicSharedMemorySize, (int)shmem);
    dim3 grid(65536 / QT, 4);
    liif_hmma_kernel<<<grid, NTHR, shmem>>>(w0, w4, b1, b2, b3, b4, (float*)d_out);
}

// round 5
// speedup vs baseline: 2.0891x; 2.0891x over previous
#include <cuda_runtime.h>
#include <cuda_fp16.h>
#include <cstdint>

// LIIF render via fp16 HMMA (mma.sync m16n8k16) on sm_103.
// R5: layer-0 folded into precomputed projection P' (R4, kept);
// 256 threads, 8 warps, warp tile 128m x 32n: each warp owns a private
// 32-col weight strip with its own cp.async double buffer -> no per-stage
// __syncthreads (only 2 barriers per layer boundary).

namespace {

constexpr int NTHR       = 256;
constexpr int QT         = 32;
constexpr int XS_H       = 264;      // X stride in halves (132 words = 4 mod 32)
constexpr int BW_H       = 40;       // B strip stride in halves (20 words)
constexpr int BW_BUF     = 32 * BW_H;          // halves per strip buffer (1280)
constexpr int NSTAGES    = 24;       // 3 layers x 8 k-tiles of 32

__device__ __half g_wh[196608];              // w1..w3 transposed [l][n][k], fp16
__device__ float  g_proj[4 * 4096 * 256];    // P' = feat@w0f + b0 + cell-terms

__device__ __forceinline__ void cp16(uint32_t dst, const void* src) {
    asm volatile("cp.async.cg.shared.global [%0], [%1], 16;"
                 :: "r"(dst), "l"(src) : "memory");
}
__device__ __forceinline__ void cp_commit() {
    asm volatile("cp.async.commit_group;" ::: "memory");
}
template <int N>
__device__ __forceinline__ void cp_wait() {
    asm volatile("cp.async.wait_group %0;" :: "n"(N) : "memory");
}
__device__ __forceinline__ uint32_t smem_u32(const void* p) {
    uint32_t a;
    asm("{ .reg .u64 t; cvta.to.shared.u64 t, %1; cvt.u32.u64 %0, t; }"
        : "=r"(a) : "l"(p));
    return a;
}
__device__ __forceinline__ void mma_f16(float c[4], uint32_t a0, uint32_t a1,
                                        uint32_t a2, uint32_t a3,
                                        uint32_t b0, uint32_t b1) {
    asm volatile(
        "mma.sync.aligned.m16n8k16.row.col.f32.f16.f16.f32 "
        "{%0,%1,%2,%3}, {%4,%5,%6,%7}, {%8,%9}, {%0,%1,%2,%3};"
        : "+f"(c[0]), "+f"(c[1]), "+f"(c[2]), "+f"(c[3])
        : "r"(a0), "r"(a1), "r"(a2), "r"(a3), "r"(b0), "r"(b1));
}

// ---------- prep 1: w1..w3 -> fp16, transposed to [l][n][k] ----------
__global__ void prep_w_kernel(const float* __restrict__ w1, const float* __restrict__ w2,
                              const float* __restrict__ w3) {
    const int idx = blockIdx.x * blockDim.x + threadIdx.x;
    if (idx >= 196608) return;
    const int l = idx >> 16;
    const int rem = idx & 65535;
    const int nn = rem >> 8, k = rem & 255;
    const float* w = (l == 0) ? w1 : (l == 1) ? w2 : w3;
    g_wh[idx] = __float2half_rn(w[k * 256 + nn]);
}

// ---------- prep 2: P'[n][idx][c] (fp32, validated R4) ----------
__global__ void prep_proj_kernel(const float* __restrict__ feat,
                                 const float* __restrict__ w0,
                                 const float* __restrict__ b0) {
    __shared__ float sf[64];
    const int blk = blockIdx.x;
    const int n   = blk >> 12;
    const int idx = blk & 4095;
    const int c   = threadIdx.x;
    if (c < 64) sf[c] = feat[((size_t)n * 64 + c) * 4096 + idx];
    __syncthreads();
    float acc = b0[c] + 0.5f * (w0[66 * 256 + c] + w0[67 * 256 + c]);
#pragma unroll 8
    for (int ch = 0; ch < 64; ch++)
        acc = fmaf(sf[ch], w0[ch * 256 + c], acc);
    g_proj[(size_t)blk * 256 + c] = acc;
}

// ---------- main kernel ----------
__global__ __launch_bounds__(NTHR, 1)
void liif_hmma_kernel(const float* __restrict__ w0, const float* __restrict__ w4,
                      const float* __restrict__ b1, const float* __restrict__ b2,
                      const float* __restrict__ b3, const float* __restrict__ b4,
                      float* __restrict__ out)
{
    extern __shared__ __half smem_h[];
    __half* Xs = smem_h;                         // 128 x 264 halves
    __half* Bs = smem_h + 128 * XS_H;            // 8 warps x 2 bufs x 1280 halves
    const uint32_t bs_u = smem_u32(Bs);

    __shared__ float s_bias[3][256];
    __shared__ float s_w0r[2][256];
    __shared__ float s_w4[772];
    __shared__ float s_b4[3];
    __shared__ int   s_idx[4][QT];
    __shared__ float s_rel[4][2][QT];
    __shared__ float s_wt[4][QT];
    __shared__ float s_red[128][2][3];

    const int tid  = threadIdx.x;
    const int wid  = tid >> 5;
    const int lane = tid & 31;
    const int g_   = lane >> 2, tig = lane & 3;
    const int n    = blockIdx.y;
    const int q0   = blockIdx.x * QT;

    // per-warp B strip copy: stage st -> buffer buf (warp-private)
    auto prefetch = [&](int buf, int st) {
        const int l2 = st >> 3, t2 = st & 7;
        const uint32_t dst0 = bs_u + (uint32_t)(wid * 2 * BW_BUF + buf * BW_BUF) * 2u;
#pragma unroll
        for (int j = 0; j < 4; j++) {
            const int e = lane + 32 * j;
            const int row = e >> 2, ch = e & 3;          // row 0..31, 16B chunk 0..3
            const __half* src = g_wh + (((l2 * 256 + wid * 32 + row) << 8) + t2 * 32 + ch * 8);
            cp16(dst0 + (uint32_t)(row * BW_H + ch * 8) * 2u, src);
        }
        cp_commit();
    };

    prefetch(0, 0);     // stage 0 in flight during setup

    for (int i = tid; i < 256; i += NTHR) {
        s_bias[0][i] = b1[i]; s_bias[1][i] = b2[i]; s_bias[2][i] = b3[i];
        s_w0r[0][i] = w0[64 * 256 + i]; s_w0r[1][i] = w0[65 * 256 + i];
    }
    for (int i = tid; i < 768; i += NTHR) s_w4[i] = w4[i];
    if (tid < 3) s_b4[tid] = b4[tid];

    // per-query geometry (validated R1/R3)
    if (tid < QT) {
        const int q = q0 + tid;
        const int yq = q >> 8, xq = q & 255;
        const float c0 = (2.f * (float)yq + 1.f) * (1.f / 256.f) - 1.f;
        const float c1 = (2.f * (float)xq + 1.f) * (1.f / 256.f) - 1.f;
        const float lo = (float)(-1.0 + 1e-6), hi = (float)(1.0 - 1e-6);
        float areas[4];
#pragma unroll
        for (int t = 0; t < 4; t++) {
            const double vx = (t < 2) ? -1.0 : 1.0;
            const double vy = (t & 1) ? 1.0 : -1.0;
            const float shx = (float)(vx * (1.0 / 64.0) + 1e-6);
            const float shy = (float)(vy * (1.0 / 64.0) + 1e-6);
            const float cc0 = fminf(fmaxf(c0 + shx, lo), hi);
            const float cc1 = fminf(fmaxf(c1 + shy, lo), hi);
            int iy = (int)rintf(((cc0 + 1.f) * 64.f - 1.f) * 0.5f);
            int ix = (int)rintf(((cc1 + 1.f) * 64.f - 1.f) * 0.5f);
            iy = min(max(iy, 0), 63); ix = min(max(ix, 0), 63);
            const float qc0 = (2.f * (float)iy + 1.f) * (1.f / 64.f) - 1.f;
            const float qc1 = (2.f * (float)ix + 1.f) * (1.f / 64.f) - 1.f;
            const float r0 = (c0 - qc0) * 64.f;
            const float r1 = (c1 - qc1) * 64.f;
            s_idx[t][tid] = iy * 64 + ix;
            s_rel[t][0][tid] = r0; s_rel[t][1][tid] = r1;
            areas[t] = fabsf(r0 * r1) + 1e-9f;
        }
        const float tot = areas[0] + areas[1] + areas[2] + areas[3];
#pragma unroll
        for (int t = 0; t < 4; t++) s_wt[t][tid] = areas[3 - t] / tot;
    }
    __syncthreads();

    // h0 build: thread = (row, 128-col half); fp32 math, round to fp16
    {
        const int row = tid >> 1, hseg = tid & 1;
        const int t = row >> 5, i = row & 31;
        const int idx = s_idx[t][i];
        const float r0 = s_rel[t][0][i], r1 = s_rel[t][1][i];
        const float4* pp = (const float4*)(g_proj + (((size_t)n << 12) + idx) * 256)
                           + hseg * 32;
        __half2* xw = (__half2*)Xs + row * 132 + hseg * 64;
#pragma unroll
        for (int j = 0; j < 32; j++) {
            const float4 p = pp[j];
            const int c = hseg * 128 + j * 4;
            const float v0 = fmaf(r0, s_w0r[0][c],     fmaf(r1, s_w0r[1][c],     p.x));
            const float v1 = fmaf(r0, s_w0r[0][c + 1], fmaf(r1, s_w0r[1][c + 1], p.y));
            const float v2 = fmaf(r0, s_w0r[0][c + 2], fmaf(r1, s_w0r[1][c + 2], p.z));
            const float v3 = fmaf(r0, s_w0r[0][c + 3], fmaf(r1, s_w0r[1][c + 3], p.w));
            xw[j * 2]     = __floats2half2_rn(fmaxf(v0, 0.f), fmaxf(v1, 0.f));
            xw[j * 2 + 1] = __floats2half2_rn(fmaxf(v2, 0.f), fmaxf(v3, 0.f));
        }
    }
    __syncthreads();

    const uint32_t* Xw = (const uint32_t*)Xs;              // half2 word view
    const uint32_t* Bw = (const uint32_t*)(Bs + wid * 2 * BW_BUF);

    float acc[8][4][4];
#pragma unroll
    for (int mt = 0; mt < 8; mt++)
#pragma unroll
        for (int nt = 0; nt < 4; nt++)
#pragma unroll
            for (int r = 0; r < 4; r++) acc[mt][nt][r] = 0.f;

    int buf = 0;
#pragma unroll 1
    for (int st = 0; st < NSTAGES; st++) {
        const int tile = st & 7;

        if (st + 1 < NSTAGES) { prefetch(buf ^ 1, st + 1); cp_wait<1>(); }
        else                  { cp_wait<0>(); }
        // no __syncthreads: B strips are warp-private, Xs is read-only here

        const uint32_t* Bb = Bw + buf * (BW_BUF / 2);
        const int kw0 = tile * 16;

#pragma unroll
        for (int s = 0; s < 2; s++) {            // two k16 steps per 32-k tile
            uint32_t b0[4], b1[4];
#pragma unroll
            for (int nt = 0; nt < 4; nt++) {
                const int bw = (nt * 8 + g_) * 20 + s * 8 + tig;
                b0[nt] = Bb[bw];
                b1[nt] = Bb[bw + 4];
            }
            const int kw = kw0 + s * 8 + tig;
#pragma unroll
            for (int mt = 0; mt < 8; mt++) {
                const int r0w = (mt * 16 + g_) * 132 + kw;
                const uint32_t a0 = Xw[r0w];
                const uint32_t a1 = Xw[r0w + 8 * 132];
                const uint32_t a2 = Xw[r0w + 4];
                const uint32_t a3 = Xw[r0w + 8 * 132 + 4];
#pragma unroll
                for (int nt = 0; nt < 4; nt++)
                    mma_f16(acc[mt][nt], a0, a1, a2, a3, b0[nt], b1[nt]);
            }
        }
        buf ^= 1;

        if (tile == 7) {                         // layer boundary
            const int le = st >> 3;
            __syncthreads();                     // all reads of Xs done
#pragma unroll
            for (int mt = 0; mt < 8; mt++) {
#pragma unroll
                for (int nt = 0; nt < 4; nt++) {
                    const int c = wid * 32 + nt * 8 + 2 * tig;
                    const float bv0 = s_bias[le][c], bv1 = s_bias[le][c + 1];
                    const float v00 = fmaxf(acc[mt][nt][0] + bv0, 0.f);
                    const float v01 = fmaxf(acc[mt][nt][1] + bv1, 0.f);
                    const float v10 = fmaxf(acc[mt][nt][2] + bv0, 0.f);
                    const float v11 = fmaxf(acc[mt][nt][3] + bv1, 0.f);
                    const int r0 = mt * 16 + g_;
                    __half2* xw = (__half2*)Xs;
                    xw[r0 * 132 + wid * 16 + nt * 4 + tig]       = __floats2half2_rn(v00, v01);
                    xw[(r0 + 8) * 132 + wid * 16 + nt * 4 + tig] = __floats2half2_rn(v10, v11);
                    acc[mt][nt][0] = 0.f; acc[mt][nt][1] = 0.f;
                    acc[mt][nt][2] = 0.f; acc[mt][nt][3] = 0.f;
                }
            }
            __syncthreads();                     // writes visible before next layer
        }
    }

    // final 256->3 layer, fp32: thread = (row, k-half)
    {
        const int row = tid >> 1, hseg = tid & 1;
        const __half2* xw = (const __half2*)Xs + row * 132 + hseg * 64;
        float a0 = 0.f, a1 = 0.f, a2 = 0.f;
#pragma unroll 16
        for (int j = 0; j < 64; j++) {
            const float2 y = __half22float2(xw[j]);
            const float* wr = &s_w4[(hseg * 128 + 2 * j) * 3];
            a0 = fmaf(y.x, wr[0], fmaf(y.y, wr[3], a0));
            a1 = fmaf(y.x, wr[1], fmaf(y.y, wr[4], a1));
            a2 = fmaf(y.x, wr[2], fmaf(y.y, wr[5], a2));
        }
        s_red[row][hseg][0] = a0; s_red[row][hseg][1] = a1; s_red[row][hseg][2] = a2;
    }
    __syncthreads();

    // area-weighted combine + NCHW write
    if (tid < 96) {
        const int i = tid / 3;
        const int o = tid - 3 * (tid / 3);
        float v = 0.f;
#pragma unroll
        for (int t = 0; t < 4; t++) {
            const int row = t * 32 + i;
            const float p = s_b4[o] + s_red[row][0][o] + s_red[row][1][o];
            v += s_wt[t][i] * p;
        }
        out[((size_t)n * 3 + o) * 65536 + q0 + i] = v;
    }
}

} // anonymous namespace

extern "C" void kernel_launch(void* const* d_in, const int* in_sizes, int n_in,
                              void* d_out, int out_size)
{
    (void)in_sizes; (void)n_in; (void)out_size;
    const float* feat = (const float*)d_in[0];
    const float* w0 = (const float*)d_in[1];
    const float* b0 = (const float*)d_in[2];
    const float* w1 = (const float*)d_in[3];
    const float* b1 = (const float*)d_in[4];
    const float* w2 = (const float*)d_in[5];
    const float* b2 = (const float*)d_in[6];
    const float* w3 = (const float*)d_in[7];
    const float* b3 = (const float*)d_in[8];
    const float* w4 = (const float*)d_in[9];
    const float* b4 = (const float*)d_in[10];

    prep_w_kernel<<<(196608 + 255) / 256, 256>>>(w1, w2, w3);
    prep_proj_kernel<<<16384, 256>>>(feat, w0, b0);

    const size_t shmem = (size_t)(128 * 264 + 8 * 2 * 32 * 40) * sizeof(__half); // 108544 B
    cudaFuncSetAttribute(liif_hmma_kernel,
                         cudaFuncAttributeMaxDynamicSharedMemorySize, (int)shmem);
    dim3 grid(65536 / 32, 4);
    liif_hmma_kernel<<<grid, 256, shmem>>>(w0, w4, b1, b2, b3, b4, (float*)d_out);
}